// round 15
// baseline (speedup 1.0000x reference)
#include <cuda_runtime.h>
#include <cuda_bf16.h>
#include <cstdint>

#define N_NODES 50000
#define N_EDGES 800000
#define F_IN    128
#define HIDDEN  256
#define N_GRAPHS 128

// ---------------- scratch (device globals; no allocation allowed) ----------
__device__ float g_bufA[(size_t)N_NODES * HIDDEN];   // 51.2 MB
__device__ float g_bufB[(size_t)N_NODES * HIDDEN];   // 51.2 MB
__device__ float g_pool[N_GRAPHS * HIDDEN];
__device__ float g_Wt1[HIDDEN * F_IN];               // W1^T : [256][128]
__device__ float g_Wt2[HIDDEN * HIDDEN];             // W2^T : [256][256]
__device__ int   g_rowptr[N_NODES + 1];
__device__ int   g_fill[N_NODES];
__device__ int   g_csr_src[N_EDGES];
__device__ float g_csr_w[N_EDGES];

// ---------------- helpers ---------------------------------------------------
__device__ __forceinline__ uint32_t f32_to_tf32(float v) {
    uint32_t o;
    asm("cvt.rna.tf32.f32 %0, %1;" : "=r"(o) : "f"(v));
    return o;
}

// split v into (hi, lo) tf32 pair: v ~= hi + lo, residual ~2^-22 * |v|
__device__ __forceinline__ uint2 tf32_split(float v) {
    uint32_t h = f32_to_tf32(v);
    float r = v - __uint_as_float(h);
    uint32_t l = f32_to_tf32(r);
    return make_uint2(h, l);
}

// XOR swizzle inside a 32-word (BK) row: conflict-free fragment access
__device__ __forceinline__ int swz(int r, int c) {
    return r * 32 + (c ^ ((r & 7) << 2));
}

__device__ __forceinline__ void mma_tf32(float* c, const uint32_t* a, const uint32_t* b) {
    asm volatile(
        "mma.sync.aligned.m16n8k8.row.col.f32.tf32.tf32.f32 "
        "{%0,%1,%2,%3}, {%4,%5,%6,%7}, {%8,%9}, {%0,%1,%2,%3};"
        : "+f"(c[0]), "+f"(c[1]), "+f"(c[2]), "+f"(c[3])
        : "r"(a[0]), "r"(a[1]), "r"(a[2]), "r"(a[3]), "r"(b[0]), "r"(b[1]));
}

// 3xtf32: acc += hi*hi + lo*hi + hi*lo  (lo*lo dropped, ~2^-22 scale)
__device__ __forceinline__ void mma3(float* c, const uint2* a, const uint2* b) {
    uint32_t ah[4] = {a[0].x, a[1].x, a[2].x, a[3].x};
    uint32_t al[4] = {a[0].y, a[1].y, a[2].y, a[3].y};
    uint32_t bh[2] = {b[0].x, b[1].x};
    uint32_t bl[2] = {b[0].y, b[1].y};
    mma_tf32(c, ah, bh);
    mma_tf32(c, al, bh);
    mma_tf32(c, ah, bl);
}

// ---------------- CSR build -------------------------------------------------
__global__ void zero_rowptr_kernel() {
    int i = blockIdx.x * blockDim.x + threadIdx.x;
    if (i <= N_NODES) g_rowptr[i] = 0;
}

__global__ void count_kernel(const int* __restrict__ edst) {
    int e = blockIdx.x * blockDim.x + threadIdx.x;
    if (e < N_EDGES) atomicAdd(&g_rowptr[edst[e] + 1], 1);
}

// single-block inclusive scan over g_rowptr[1..N_NODES]; also writes g_fill
__global__ void scan_kernel() {
    __shared__ int warpsums[32];
    __shared__ int carry;
    int tid = threadIdx.x, lane = tid & 31, wid = tid >> 5;
    if (tid == 0) { carry = 0; g_fill[0] = 0; }
    __syncthreads();
    for (int base = 1; base <= N_NODES; base += 1024) {
        int i = base + tid;
        int v = (i <= N_NODES) ? g_rowptr[i] : 0;
        int x = v;
        #pragma unroll
        for (int off = 1; off < 32; off <<= 1) {
            int y = __shfl_up_sync(0xffffffffu, x, off);
            if (lane >= off) x += y;
        }
        if (lane == 31) warpsums[wid] = x;
        __syncthreads();
        if (wid == 0) {
            int s = warpsums[lane];
            #pragma unroll
            for (int off = 1; off < 32; off <<= 1) {
                int y = __shfl_up_sync(0xffffffffu, s, off);
                if (lane >= off) s += y;
            }
            warpsums[lane] = s;
        }
        __syncthreads();
        int prefix = carry + x + (wid ? warpsums[wid - 1] : 0);
        int total  = warpsums[31];
        if (i <= N_NODES) {
            g_rowptr[i] = prefix;
            if (i < N_NODES) g_fill[i] = prefix;   // fill_init folded in
        }
        __syncthreads();
        if (tid == 0) carry += total;
        __syncthreads();
    }
}

__global__ void scatter_kernel(const int* __restrict__ esrc,
                               const int* __restrict__ edst,
                               const float* __restrict__ ew) {
    int e = blockIdx.x * blockDim.x + threadIdx.x;
    if (e < N_EDGES) {
        int slot = atomicAdd(&g_fill[edst[e]], 1);
        g_csr_src[slot] = esrc[e];
        g_csr_w[slot]   = ew[e];
    }
}

// ---------------- weight transpose: Wt[n][k] = W[k][n] ----------------------
__global__ void transpose_kernel(const float* __restrict__ W, float* __restrict__ Wt,
                                 int K, int N) {
    __shared__ float tile[32][33];
    int bx = blockIdx.x * 32, by = blockIdx.y * 32;
    int x = bx + threadIdx.x;
    int y = by + threadIdx.y;
    #pragma unroll
    for (int j = 0; j < 32; j += 8)
        if (y + j < K && x < N) tile[threadIdx.y + j][threadIdx.x] = W[(y + j) * N + x];
    __syncthreads();
    x = by + threadIdx.x;
    y = bx + threadIdx.y;
    #pragma unroll
    for (int j = 0; j < 32; j += 8)
        if (y + j < N && x < K) Wt[(y + j) * K + x] = tile[threadIdx.x][threadIdx.y + j];
}

// ---------------- 3xtf32 mma GEMM: C = relu(A @ Bt^T + bias) ----------------
// A: [M, KTOT] fp32 row-major. Bt: [256, KTOT] (output-col-major, K contiguous).
// CTA: BM=128 x BN=64, BK=32, 256 threads = 8 warps (4 M x 2 N), warp tile 32x32.
// smem holds (hi,lo) tf32 pairs; double buffered: 2*(128*32 + 64*32)*8B = 96KB.
template<int KTOT, bool RELU>
__global__ __launch_bounds__(256, 2)
void mma_gemm_kernel(const float* __restrict__ A,
                     const float* __restrict__ Bt,
                     const float* __restrict__ bias,
                     float* __restrict__ C, int M) {
    extern __shared__ uint2 smem_dyn[];
    uint2* sA[2] = { smem_dyn,               smem_dyn + 128 * 32 };
    uint2* sB[2] = { smem_dyn + 2*128*32,    smem_dyn + 2*128*32 + 64 * 32 };

    const int tid = threadIdx.x;
    const int lane = tid & 31, wid = tid >> 5;
    const int warp_m = wid & 3, warp_n = wid >> 2;
    const int row0 = blockIdx.y * 128;
    const int col0 = blockIdx.x * 64;

    float acc[2][4][4];
    #pragma unroll
    for (int i = 0; i < 2; i++)
        #pragma unroll
        for (int j = 0; j < 4; j++)
            #pragma unroll
            for (int k = 0; k < 4; k++) acc[i][j][k] = 0.f;

    const int NT = KTOT / 32;
    float4 rgA[4];   // 128x32 tile: 1024 float4, 4/thread
    float4 rgB[2];   // 64x32 tile:   512 float4, 2/thread

    auto ldg_tile = [&](int t) {
        #pragma unroll
        for (int q = 0; q < 4; q++) {
            int f = tid + q * 256;
            int r = f >> 3, c4 = f & 7;
            float4 v = make_float4(0.f, 0.f, 0.f, 0.f);
            if (row0 + r < M)
                v = *reinterpret_cast<const float4*>(
                        &A[(size_t)(row0 + r) * KTOT + t * 32 + c4 * 4]);
            rgA[q] = v;
        }
        #pragma unroll
        for (int q = 0; q < 2; q++) {
            int f = tid + q * 256;
            int r = f >> 3, c4 = f & 7;
            rgB[q] = *reinterpret_cast<const float4*>(
                        &Bt[(size_t)(col0 + r) * KTOT + t * 32 + c4 * 4]);
        }
    };
    auto sts_tile = [&](int s) {
        #pragma unroll
        for (int q = 0; q < 4; q++) {
            int f = tid + q * 256;
            int r = f >> 3, c4 = f & 7;
            uint2* p = &sA[s][swz(r, c4 * 4)];   // swizzle keeps low 2 bits -> contiguous 4
            p[0] = tf32_split(rgA[q].x); p[1] = tf32_split(rgA[q].y);
            p[2] = tf32_split(rgA[q].z); p[3] = tf32_split(rgA[q].w);
        }
        #pragma unroll
        for (int q = 0; q < 2; q++) {
            int f = tid + q * 256;
            int r = f >> 3, c4 = f & 7;
            uint2* p = &sB[s][swz(r, c4 * 4)];
            p[0] = tf32_split(rgB[q].x); p[1] = tf32_split(rgB[q].y);
            p[2] = tf32_split(rgB[q].z); p[3] = tf32_split(rgB[q].w);
        }
    };

    ldg_tile(0);
    sts_tile(0);
    __syncthreads();

    for (int t = 0; t < NT; t++) {
        if (t + 1 < NT) ldg_tile(t + 1);
        const uint2* cA = sA[t & 1];
        const uint2* cB = sB[t & 1];
        const int g = lane >> 2, q = lane & 3;
        #pragma unroll
        for (int kk = 0; kk < 4; kk++) {
            uint2 af[2][4];
            #pragma unroll
            for (int mf = 0; mf < 2; mf++) {
                int r = warp_m * 32 + mf * 16 + g;
                int c = kk * 8 + q;
                af[mf][0] = cA[swz(r,     c)];
                af[mf][1] = cA[swz(r + 8, c)];
                af[mf][2] = cA[swz(r,     c + 4)];
                af[mf][3] = cA[swz(r + 8, c + 4)];
            }
            uint2 bf[4][2];
            #pragma unroll
            for (int nf = 0; nf < 4; nf++) {
                int r = warp_n * 32 + nf * 8 + g;
                int c = kk * 8 + q;
                bf[nf][0] = cB[swz(r, c)];
                bf[nf][1] = cB[swz(r, c + 4)];
            }
            #pragma unroll
            for (int mf = 0; mf < 2; mf++)
                #pragma unroll
                for (int nf = 0; nf < 4; nf++)
                    mma3(acc[mf][nf], af[mf], bf[nf]);
        }
        if (t + 1 < NT) sts_tile((t + 1) & 1);
        __syncthreads();
    }

    // epilogue: bias + optional relu, float2 stores
    const int g = lane >> 2, q = lane & 3;
    #pragma unroll
    for (int mf = 0; mf < 2; mf++) {
        #pragma unroll
        for (int half = 0; half < 2; half++) {
            int grow = row0 + warp_m * 32 + mf * 16 + half * 8 + g;
            if (grow >= M) continue;
            #pragma unroll
            for (int nf = 0; nf < 4; nf++) {
                int gcol = col0 + warp_n * 32 + nf * 8 + 2 * q;
                float v0 = acc[mf][nf][half * 2 + 0] + __ldg(&bias[gcol]);
                float v1 = acc[mf][nf][half * 2 + 1] + __ldg(&bias[gcol + 1]);
                if (RELU) { v0 = fmaxf(v0, 0.f); v1 = fmaxf(v1, 0.f); }
                *reinterpret_cast<float2*>(&C[(size_t)grow * 256 + gcol]) =
                    make_float2(v0, v1);
            }
        }
    }
}

// ---------------- SPMM: one warp per dst node, float4 lanes, unroll 2 -------
template<int W>  // 128 or 256
__global__ __launch_bounds__(256)
void spmm_kernel(const float* __restrict__ t, float* __restrict__ out) {
    int wid = threadIdx.x >> 5, lane = threadIdx.x & 31;
    int node = blockIdx.x * 8 + wid;
    if (node >= N_NODES) return;
    int start = g_rowptr[node];
    int end   = g_rowptr[node + 1];

    float4 p0 = make_float4(0.f, 0.f, 0.f, 0.f);
    float4 p1 = make_float4(0.f, 0.f, 0.f, 0.f);
    float4 q0 = make_float4(0.f, 0.f, 0.f, 0.f);
    float4 q1 = make_float4(0.f, 0.f, 0.f, 0.f);

    for (int base = start; base < end; base += 32) {
        int idx = base + lane;
        int   s  = (idx < end) ? g_csr_src[idx] : 0;
        float wv = (idx < end) ? g_csr_w[idx]   : 0.f;
        int cnt = min(32, end - base);
        int i = 0;
        for (; i + 1 < cnt; i += 2) {
            int   s0 = __shfl_sync(0xffffffffu, s,  i);
            int   s1 = __shfl_sync(0xffffffffu, s,  i + 1);
            float w0 = __shfl_sync(0xffffffffu, wv, i);
            float w1 = __shfl_sync(0xffffffffu, wv, i + 1);
            const float4* r0 = reinterpret_cast<const float4*>(t + (size_t)s0 * W);
            const float4* r1 = reinterpret_cast<const float4*>(t + (size_t)s1 * W);
            float4 a = r0[lane];
            float4 b = r1[lane];
            p0.x = fmaf(a.x, w0, p0.x); p0.y = fmaf(a.y, w0, p0.y);
            p0.z = fmaf(a.z, w0, p0.z); p0.w = fmaf(a.w, w0, p0.w);
            q0.x = fmaf(b.x, w1, q0.x); q0.y = fmaf(b.y, w1, q0.y);
            q0.z = fmaf(b.z, w1, q0.z); q0.w = fmaf(b.w, w1, q0.w);
            if (W == 256) {
                float4 a1 = r0[lane + 32];
                float4 b1 = r1[lane + 32];
                p1.x = fmaf(a1.x, w0, p1.x); p1.y = fmaf(a1.y, w0, p1.y);
                p1.z = fmaf(a1.z, w0, p1.z); p1.w = fmaf(a1.w, w0, p1.w);
                q1.x = fmaf(b1.x, w1, q1.x); q1.y = fmaf(b1.y, w1, q1.y);
                q1.z = fmaf(b1.z, w1, q1.z); q1.w = fmaf(b1.w, w1, q1.w);
            }
        }
        if (i < cnt) {
            int   s0 = __shfl_sync(0xffffffffu, s,  i);
            float w0 = __shfl_sync(0xffffffffu, wv, i);
            const float4* r0 = reinterpret_cast<const float4*>(t + (size_t)s0 * W);
            float4 a = r0[lane];
            p0.x = fmaf(a.x, w0, p0.x); p0.y = fmaf(a.y, w0, p0.y);
            p0.z = fmaf(a.z, w0, p0.z); p0.w = fmaf(a.w, w0, p0.w);
            if (W == 256) {
                float4 a1 = r0[lane + 32];
                p1.x = fmaf(a1.x, w0, p1.x); p1.y = fmaf(a1.y, w0, p1.y);
                p1.z = fmaf(a1.z, w0, p1.z); p1.w = fmaf(a1.w, w0, p1.w);
            }
        }
    }
    float4* orow = reinterpret_cast<float4*>(out + (size_t)node * W);
    orow[lane] = make_float4(p0.x + q0.x, p0.y + q0.y, p0.z + q0.z, p0.w + q0.w);
    if (W == 256)
        orow[lane + 32] = make_float4(p1.x + q1.x, p1.y + q1.y, p1.z + q1.z, p1.w + q1.w);
}

// ---------------- segment pool (seg_ids are sorted) -------------------------
__global__ __launch_bounds__(HIDDEN)
void pool_kernel(const float* __restrict__ h, const int* __restrict__ seg) {
    int gi = blockIdx.x, tid = threadIdx.x;
    int lo = 0, hi = N_NODES;
    while (lo < hi) { int mid = (lo + hi) >> 1; if (seg[mid] < gi) lo = mid + 1; else hi = mid; }
    int start = lo;
    hi = N_NODES;
    while (lo < hi) { int mid = (lo + hi) >> 1; if (seg[mid] < gi + 1) lo = mid + 1; else hi = mid; }
    int end = lo;
    float a0 = 0.f, a1 = 0.f, a2 = 0.f, a3 = 0.f;
    int i = start;
    for (; i + 3 < end; i += 4) {
        a0 += h[(size_t)(i + 0) * HIDDEN + tid];
        a1 += h[(size_t)(i + 1) * HIDDEN + tid];
        a2 += h[(size_t)(i + 2) * HIDDEN + tid];
        a3 += h[(size_t)(i + 3) * HIDDEN + tid];
    }
    for (; i < end; i++) a0 += h[(size_t)i * HIDDEN + tid];
    g_pool[gi * HIDDEN + tid] = (a0 + a1) + (a2 + a3);
}

// ---------------- dense head: out[g] = relu(pool@Wd+bd) @ Wo + bo -----------
__global__ __launch_bounds__(HIDDEN)
void head_kernel(const float* __restrict__ Wd, const float* __restrict__ bd,
                 const float* __restrict__ Wo, const float* __restrict__ bo,
                 float* __restrict__ out) {
    __shared__ float s_g[HIDDEN];
    __shared__ float s_red[HIDDEN];
    int gi = blockIdx.x, j = threadIdx.x;
    s_g[j] = g_pool[gi * HIDDEN + j];
    __syncthreads();
    float acc = bd[j];
    #pragma unroll 8
    for (int k = 0; k < HIDDEN; k++)
        acc += s_g[k] * Wd[k * HIDDEN + j];
    acc = fmaxf(acc, 0.f);
    s_red[j] = acc * Wo[j];
    __syncthreads();
    for (int s = HIDDEN / 2; s > 0; s >>= 1) {
        if (j < s) s_red[j] += s_red[j + s];
        __syncthreads();
    }
    if (j == 0) out[gi] = s_red[0] + bo[0];
}

// ---------------- launch ----------------------------------------------------
extern "C" void kernel_launch(void* const* d_in, const int* in_sizes, int n_in,
                              void* d_out, int out_size) {
    const float* x    = (const float*)d_in[0];
    const int*   esrc = (const int*)  d_in[1];
    const int*   edst = (const int*)  d_in[2];
    const float* ew   = (const float*)d_in[3];
    const int*   seg  = (const int*)  d_in[4];
    const float* W1   = (const float*)d_in[5];
    const float* b1   = (const float*)d_in[6];
    const float* W2   = (const float*)d_in[7];
    const float* b2   = (const float*)d_in[8];
    const float* Wd   = (const float*)d_in[9];
    const float* bd   = (const float*)d_in[10];
    const float* Wo   = (const float*)d_in[11];
    const float* bo   = (const float*)d_in[12];
    float* out = (float*)d_out;

    float* bufA; cudaGetSymbolAddress((void**)&bufA, g_bufA);
    float* bufB; cudaGetSymbolAddress((void**)&bufB, g_bufB);
    float* Wt1;  cudaGetSymbolAddress((void**)&Wt1,  g_Wt1);
    float* Wt2;  cudaGetSymbolAddress((void**)&Wt2,  g_Wt2);

    const size_t smem_bytes = (size_t)(2 * 128 * 32 + 2 * 64 * 32) * sizeof(uint2); // 96KB
    cudaFuncSetAttribute(mma_gemm_kernel<F_IN,  true>,
                         cudaFuncAttributeMaxDynamicSharedMemorySize, (int)smem_bytes);
    cudaFuncSetAttribute(mma_gemm_kernel<HIDDEN, true>,
                         cudaFuncAttributeMaxDynamicSharedMemorySize, (int)smem_bytes);

    // --- weight transposes (tiny) ---
    {
        dim3 blk(32, 8);
        dim3 g1(HIDDEN / 32, F_IN / 32);
        transpose_kernel<<<g1, blk>>>(W1, Wt1, F_IN, HIDDEN);
        dim3 g2(HIDDEN / 32, HIDDEN / 32);
        transpose_kernel<<<g2, blk>>>(W2, Wt2, HIDDEN, HIDDEN);
    }

    // --- CSR build (by destination) ---
    zero_rowptr_kernel<<<(N_NODES + 256) / 256, 256>>>();
    count_kernel<<<(N_EDGES + 255) / 256, 256>>>(edst);
    scan_kernel<<<1, 1024>>>();   // also initializes g_fill
    scatter_kernel<<<(N_EDGES + 255) / 256, 256>>>(esrc, edst, ew);

    const int n_mtiles = (N_NODES + 127) / 128;

    // --- layer 1: s0 = spmm(x) [N,128]; h1 = relu(s0 @ W1 + b1) ---
    spmm_kernel<F_IN><<<(N_NODES + 7) / 8, 256>>>(x, bufA);
    mma_gemm_kernel<F_IN, true><<<dim3(4, n_mtiles), 256, smem_bytes>>>(
        bufA, Wt1, b1, bufB, N_NODES);

    // --- layer 2: s1 = spmm(h1) [N,256]; h2 = relu(s1 @ W2 + b2) ---
    spmm_kernel<HIDDEN><<<(N_NODES + 7) / 8, 256>>>(bufB, bufA);
    mma_gemm_kernel<HIDDEN, true><<<dim3(4, n_mtiles), 256, smem_bytes>>>(
        bufA, Wt2, b2, bufB, N_NODES);

    // --- pool + head ---
    pool_kernel<<<N_GRAPHS, HIDDEN>>>(bufB, seg);
    head_kernel<<<N_GRAPHS, HIDDEN>>>(Wd, bd, Wo, bo, out);
}

// round 16
// speedup vs baseline: 2.4418x; 2.4418x over previous
#include <cuda_runtime.h>
#include <cuda_bf16.h>
#include <cstdint>

#define N_NODES 50000
#define N_EDGES 800000
#define F_IN    128
#define HIDDEN  256
#define N_GRAPHS 128

// ---------------- scratch (device globals; no allocation allowed) ----------
__device__ float g_bufA[(size_t)N_NODES * HIDDEN];   // 51.2 MB
__device__ float g_bufB[(size_t)N_NODES * HIDDEN];   // 51.2 MB
__device__ float g_pool[N_GRAPHS * HIDDEN];
__device__ float g_Wt1[HIDDEN * F_IN];               // W1^T : [256][128]
__device__ float g_Wt2[HIDDEN * HIDDEN];             // W2^T : [256][256]
__device__ int   g_rowptr[N_NODES + 1];
__device__ int   g_fill[N_NODES];
__device__ int2  g_csr[N_EDGES];                     // (src, w-bits) packed

// ---------------- helpers ---------------------------------------------------
// split (v0,v1) into bf16x2 hi word + bf16x2 lo word; v ~= hi + lo, |res|<=2^-18|v|
__device__ __forceinline__ void bf16_split2(float vx, float vy,
                                            uint32_t& hw, uint32_t& lw) {
    __nv_bfloat162 h = __floats2bfloat162_rn(vx, vy);
    float hx = __low2float(h);
    float hy = __high2float(h);
    __nv_bfloat162 l = __floats2bfloat162_rn(vx - hx, vy - hy);
    hw = *reinterpret_cast<uint32_t*>(&h);
    lw = *reinterpret_cast<uint32_t*>(&l);
}

// swizzle for 16-word (bf16x2) rows: conflict-free fragment access
// (rows repeat in bank space every 2; distinguish r>>1 mod 4 via bits [2:3])
__device__ __forceinline__ int swz16(int r, int p) {
    return r * 16 + (p ^ (((r >> 1) & 3) << 2));
}

__device__ __forceinline__ void mma_bf16(float* c, const uint32_t* a, const uint32_t* b) {
    asm volatile(
        "mma.sync.aligned.m16n8k16.row.col.f32.bf16.bf16.f32 "
        "{%0,%1,%2,%3}, {%4,%5,%6,%7}, {%8,%9}, {%0,%1,%2,%3};"
        : "+f"(c[0]), "+f"(c[1]), "+f"(c[2]), "+f"(c[3])
        : "r"(a[0]), "r"(a[1]), "r"(a[2]), "r"(a[3]), "r"(b[0]), "r"(b[1]));
}

// ---------------- CSR build -------------------------------------------------
__global__ void zero_rowptr_kernel() {
    int i = blockIdx.x * blockDim.x + threadIdx.x;
    if (i <= N_NODES) g_rowptr[i] = 0;
}

__global__ void count_kernel(const int* __restrict__ edst) {
    int e = blockIdx.x * blockDim.x + threadIdx.x;
    if (e < N_EDGES) atomicAdd(&g_rowptr[edst[e] + 1], 1);
}

// single-block inclusive scan over g_rowptr[1..N_NODES]; also writes g_fill
__global__ void scan_kernel() {
    __shared__ int warpsums[32];
    __shared__ int carry;
    int tid = threadIdx.x, lane = tid & 31, wid = tid >> 5;
    if (tid == 0) { carry = 0; g_fill[0] = 0; }
    __syncthreads();
    for (int base = 1; base <= N_NODES; base += 1024) {
        int i = base + tid;
        int v = (i <= N_NODES) ? g_rowptr[i] : 0;
        int x = v;
        #pragma unroll
        for (int off = 1; off < 32; off <<= 1) {
            int y = __shfl_up_sync(0xffffffffu, x, off);
            if (lane >= off) x += y;
        }
        if (lane == 31) warpsums[wid] = x;
        __syncthreads();
        if (wid == 0) {
            int s = warpsums[lane];
            #pragma unroll
            for (int off = 1; off < 32; off <<= 1) {
                int y = __shfl_up_sync(0xffffffffu, s, off);
                if (lane >= off) s += y;
            }
            warpsums[lane] = s;
        }
        __syncthreads();
        int prefix = carry + x + (wid ? warpsums[wid - 1] : 0);
        int total  = warpsums[31];
        if (i <= N_NODES) {
            g_rowptr[i] = prefix;
            if (i < N_NODES) g_fill[i] = prefix;
        }
        __syncthreads();
        if (tid == 0) carry += total;
        __syncthreads();
    }
}

__global__ void scatter_kernel(const int* __restrict__ esrc,
                               const int* __restrict__ edst,
                               const float* __restrict__ ew) {
    int e = blockIdx.x * blockDim.x + threadIdx.x;
    if (e < N_EDGES) {
        int slot = atomicAdd(&g_fill[edst[e]], 1);
        g_csr[slot] = make_int2(esrc[e], __float_as_int(ew[e]));
    }
}

// ---------------- weight transpose: Wt[n][k] = W[k][n] ----------------------
__global__ void transpose_kernel(const float* __restrict__ W, float* __restrict__ Wt,
                                 int K, int N) {
    __shared__ float tile[32][33];
    int bx = blockIdx.x * 32, by = blockIdx.y * 32;
    int x = bx + threadIdx.x;
    int y = by + threadIdx.y;
    #pragma unroll
    for (int j = 0; j < 32; j += 8)
        if (y + j < K && x < N) tile[threadIdx.y + j][threadIdx.x] = W[(y + j) * N + x];
    __syncthreads();
    x = by + threadIdx.x;
    y = bx + threadIdx.y;
    #pragma unroll
    for (int j = 0; j < 32; j += 8)
        if (y + j < N && x < K) Wt[(y + j) * K + x] = tile[threadIdx.x][threadIdx.y + j];
}

// ---------------- split-bf16 3-pass mma GEMM: C = relu(A @ Bt^T + bias) -----
// A: [M, KTOT] fp32 row-major. Bt: [256, KTOT] (output-col-major, K contiguous).
// CTA: BM=128 x BN=64, BK=32 fp32 (= 2 k16 steps), 256 threads = 8 warps (4Mx2N).
// smem: hi/lo bf16x2 plane pairs, double buffered:
//   per buffer: Ah 2048w + Al 2048w + Bh 1024w + Bl 1024w = 6144 words = 24KB
//   total 48KB.  acc += Ahi*Bhi + Alo*Bhi + Ahi*Blo  (lo*lo ~2^-18, dropped)
template<int KTOT, bool RELU>
__global__ __launch_bounds__(256)
void mma_gemm_kernel(const float* __restrict__ A,
                     const float* __restrict__ Bt,
                     const float* __restrict__ bias,
                     float* __restrict__ C, int M) {
    extern __shared__ uint32_t sm[];

    const int tid = threadIdx.x;
    const int lane = tid & 31, wid = tid >> 5;
    const int warp_m = wid & 3, warp_n = wid >> 2;
    const int row0 = blockIdx.y * 128;
    const int col0 = blockIdx.x * 64;

    float acc[2][4][4];
    #pragma unroll
    for (int i = 0; i < 2; i++)
        #pragma unroll
        for (int j = 0; j < 4; j++)
            #pragma unroll
            for (int k = 0; k < 4; k++) acc[i][j][k] = 0.f;

    const int NT = KTOT / 32;
    float4 rgA[4];   // 128x32 fp32 tile: 1024 float4, 4/thread
    float4 rgB[2];   // 64x32 fp32 tile:   512 float4, 2/thread

    auto ldg_tile = [&](int t) {
        #pragma unroll
        for (int q = 0; q < 4; q++) {
            int f = tid + q * 256;
            int r = f >> 3, c4 = f & 7;
            float4 v = make_float4(0.f, 0.f, 0.f, 0.f);
            if (row0 + r < M)
                v = *reinterpret_cast<const float4*>(
                        &A[(size_t)(row0 + r) * KTOT + t * 32 + c4 * 4]);
            rgA[q] = v;
        }
        #pragma unroll
        for (int q = 0; q < 2; q++) {
            int f = tid + q * 256;
            int r = f >> 3, c4 = f & 7;
            rgB[q] = *reinterpret_cast<const float4*>(
                        &Bt[(size_t)(col0 + r) * KTOT + t * 32 + c4 * 4]);
        }
    };
    auto sts_tile = [&](int s) {
        uint32_t* Ah = sm + s * 6144;
        uint32_t* Al = Ah + 2048;
        uint32_t* Bh = Al + 2048;
        uint32_t* Bl = Bh + 1024;
        #pragma unroll
        for (int q = 0; q < 4; q++) {
            int f = tid + q * 256;
            int r = f >> 3, c4 = f & 7;
            uint32_t h0, l0, h1, l1;
            bf16_split2(rgA[q].x, rgA[q].y, h0, l0);
            bf16_split2(rgA[q].z, rgA[q].w, h1, l1);
            int off = swz16(r, c4 * 2);                 // even -> 8B aligned
            *reinterpret_cast<uint2*>(&Ah[off]) = make_uint2(h0, h1);
            *reinterpret_cast<uint2*>(&Al[off]) = make_uint2(l0, l1);
        }
        #pragma unroll
        for (int q = 0; q < 2; q++) {
            int f = tid + q * 256;
            int r = f >> 3, c4 = f & 7;
            uint32_t h0, l0, h1, l1;
            bf16_split2(rgB[q].x, rgB[q].y, h0, l0);
            bf16_split2(rgB[q].z, rgB[q].w, h1, l1);
            int off = swz16(r, c4 * 2);
            *reinterpret_cast<uint2*>(&Bh[off]) = make_uint2(h0, h1);
            *reinterpret_cast<uint2*>(&Bl[off]) = make_uint2(l0, l1);
        }
    };

    ldg_tile(0);
    sts_tile(0);
    __syncthreads();

    const int g = lane >> 2, q = lane & 3;
    for (int t = 0; t < NT; t++) {
        if (t + 1 < NT) ldg_tile(t + 1);
        const uint32_t* Ah = sm + (t & 1) * 6144;
        const uint32_t* Al = Ah + 2048;
        const uint32_t* Bh = Al + 2048;
        const uint32_t* Bl = Bh + 1024;
        #pragma unroll
        for (int kk = 0; kk < 2; kk++) {            // two k16 steps per BK=32
            int p0 = kk * 8 + q;
            uint32_t ah[2][4], al[2][4];
            #pragma unroll
            for (int mf = 0; mf < 2; mf++) {
                int r = warp_m * 32 + mf * 16 + g;
                int i0 = swz16(r,     p0),  i1 = swz16(r + 8, p0);
                int i2 = swz16(r,     p0 + 4), i3 = swz16(r + 8, p0 + 4);
                ah[mf][0] = Ah[i0]; ah[mf][1] = Ah[i1];
                ah[mf][2] = Ah[i2]; ah[mf][3] = Ah[i3];
                al[mf][0] = Al[i0]; al[mf][1] = Al[i1];
                al[mf][2] = Al[i2]; al[mf][3] = Al[i3];
            }
            #pragma unroll
            for (int nf = 0; nf < 4; nf++) {
                int r = warp_n * 32 + nf * 8 + g;
                int i0 = swz16(r, p0), i1 = swz16(r, p0 + 4);
                uint32_t bh[2] = { Bh[i0], Bh[i1] };
                uint32_t bl[2] = { Bl[i0], Bl[i1] };
                #pragma unroll
                for (int mf = 0; mf < 2; mf++) {
                    mma_bf16(acc[mf][nf], ah[mf], bh);   // hi*hi
                    mma_bf16(acc[mf][nf], al[mf], bh);   // lo*hi
                    mma_bf16(acc[mf][nf], ah[mf], bl);   // hi*lo
                }
            }
        }
        if (t + 1 < NT) sts_tile((t + 1) & 1);
        __syncthreads();
    }

    // epilogue: bias + optional relu, float2 stores (C layout of m16n8 as k8)
    #pragma unroll
    for (int mf = 0; mf < 2; mf++) {
        #pragma unroll
        for (int half = 0; half < 2; half++) {
            int grow = row0 + warp_m * 32 + mf * 16 + half * 8 + g;
            if (grow >= M) continue;
            #pragma unroll
            for (int nf = 0; nf < 4; nf++) {
                int gcol = col0 + warp_n * 32 + nf * 8 + 2 * q;
                float v0 = acc[mf][nf][half * 2 + 0] + __ldg(&bias[gcol]);
                float v1 = acc[mf][nf][half * 2 + 1] + __ldg(&bias[gcol + 1]);
                if (RELU) { v0 = fmaxf(v0, 0.f); v1 = fmaxf(v1, 0.f); }
                *reinterpret_cast<float2*>(&C[(size_t)grow * 256 + gcol]) =
                    make_float2(v0, v1);
            }
        }
    }
}

// ---------------- SPMM: one warp per dst node, float4 lanes, unroll 2 -------
template<int W>  // 128 or 256
__global__ __launch_bounds__(256)
void spmm_kernel(const float* __restrict__ t, float* __restrict__ out) {
    int wid = threadIdx.x >> 5, lane = threadIdx.x & 31;
    int node = blockIdx.x * 8 + wid;
    if (node >= N_NODES) return;
    int start = g_rowptr[node];
    int end   = g_rowptr[node + 1];

    float4 p0 = make_float4(0.f, 0.f, 0.f, 0.f);
    float4 p1 = make_float4(0.f, 0.f, 0.f, 0.f);
    float4 q0 = make_float4(0.f, 0.f, 0.f, 0.f);
    float4 q1 = make_float4(0.f, 0.f, 0.f, 0.f);

    for (int base = start; base < end; base += 32) {
        int idx = base + lane;
        int2 e = (idx < end) ? g_csr[idx] : make_int2(0, 0);
        int   s  = e.x;
        float wv = __int_as_float(e.y);
        int cnt = min(32, end - base);
        int i = 0;
        for (; i + 1 < cnt; i += 2) {
            int   s0 = __shfl_sync(0xffffffffu, s,  i);
            int   s1 = __shfl_sync(0xffffffffu, s,  i + 1);
            float w0 = __shfl_sync(0xffffffffu, wv, i);
            float w1 = __shfl_sync(0xffffffffu, wv, i + 1);
            const float4* r0 = reinterpret_cast<const float4*>(t + (size_t)s0 * W);
            const float4* r1 = reinterpret_cast<const float4*>(t + (size_t)s1 * W);
            float4 a = r0[lane];
            float4 b = r1[lane];
            p0.x = fmaf(a.x, w0, p0.x); p0.y = fmaf(a.y, w0, p0.y);
            p0.z = fmaf(a.z, w0, p0.z); p0.w = fmaf(a.w, w0, p0.w);
            q0.x = fmaf(b.x, w1, q0.x); q0.y = fmaf(b.y, w1, q0.y);
            q0.z = fmaf(b.z, w1, q0.z); q0.w = fmaf(b.w, w1, q0.w);
            if (W == 256) {
                float4 a1 = r0[lane + 32];
                float4 b1 = r1[lane + 32];
                p1.x = fmaf(a1.x, w0, p1.x); p1.y = fmaf(a1.y, w0, p1.y);
                p1.z = fmaf(a1.z, w0, p1.z); p1.w = fmaf(a1.w, w0, p1.w);
                q1.x = fmaf(b1.x, w1, q1.x); q1.y = fmaf(b1.y, w1, q1.y);
                q1.z = fmaf(b1.z, w1, q1.z); q1.w = fmaf(b1.w, w1, q1.w);
            }
        }
        if (i < cnt) {
            int   s0 = __shfl_sync(0xffffffffu, s,  i);
            float w0 = __shfl_sync(0xffffffffu, wv, i);
            const float4* r0 = reinterpret_cast<const float4*>(t + (size_t)s0 * W);
            float4 a = r0[lane];
            p0.x = fmaf(a.x, w0, p0.x); p0.y = fmaf(a.y, w0, p0.y);
            p0.z = fmaf(a.z, w0, p0.z); p0.w = fmaf(a.w, w0, p0.w);
            if (W == 256) {
                float4 a1 = r0[lane + 32];
                p1.x = fmaf(a1.x, w0, p1.x); p1.y = fmaf(a1.y, w0, p1.y);
                p1.z = fmaf(a1.z, w0, p1.z); p1.w = fmaf(a1.w, w0, p1.w);
            }
        }
    }
    float4* orow = reinterpret_cast<float4*>(out + (size_t)node * W);
    orow[lane] = make_float4(p0.x + q0.x, p0.y + q0.y, p0.z + q0.z, p0.w + q0.w);
    if (W == 256)
        orow[lane + 32] = make_float4(p1.x + q1.x, p1.y + q1.y, p1.z + q1.z, p1.w + q1.w);
}

// ---------------- segment pool (seg_ids are sorted) -------------------------
__global__ __launch_bounds__(HIDDEN)
void pool_kernel(const float* __restrict__ h, const int* __restrict__ seg) {
    int gi = blockIdx.x, tid = threadIdx.x;
    int lo = 0, hi = N_NODES;
    while (lo < hi) { int mid = (lo + hi) >> 1; if (seg[mid] < gi) lo = mid + 1; else hi = mid; }
    int start = lo;
    hi = N_NODES;
    while (lo < hi) { int mid = (lo + hi) >> 1; if (seg[mid] < gi + 1) lo = mid + 1; else hi = mid; }
    int end = lo;
    float a0 = 0.f, a1 = 0.f, a2 = 0.f, a3 = 0.f;
    int i = start;
    for (; i + 3 < end; i += 4) {
        a0 += h[(size_t)(i + 0) * HIDDEN + tid];
        a1 += h[(size_t)(i + 1) * HIDDEN + tid];
        a2 += h[(size_t)(i + 2) * HIDDEN + tid];
        a3 += h[(size_t)(i + 3) * HIDDEN + tid];
    }
    for (; i < end; i++) a0 += h[(size_t)i * HIDDEN + tid];
    g_pool[gi * HIDDEN + tid] = (a0 + a1) + (a2 + a3);
}

// ---------------- dense head: out[g] = relu(pool@Wd+bd) @ Wo + bo -----------
__global__ __launch_bounds__(HIDDEN)
void head_kernel(const float* __restrict__ Wd, const float* __restrict__ bd,
                 const float* __restrict__ Wo, const float* __restrict__ bo,
                 float* __restrict__ out) {
    __shared__ float s_g[HIDDEN];
    __shared__ float s_red[HIDDEN];
    int gi = blockIdx.x, j = threadIdx.x;
    s_g[j] = g_pool[gi * HIDDEN + j];
    __syncthreads();
    float acc = bd[j];
    #pragma unroll 8
    for (int k = 0; k < HIDDEN; k++)
        acc += s_g[k] * Wd[k * HIDDEN + j];
    acc = fmaxf(acc, 0.f);
    s_red[j] = acc * Wo[j];
    __syncthreads();
    for (int s = HIDDEN / 2; s > 0; s >>= 1) {
        if (j < s) s_red[j] += s_red[j + s];
        __syncthreads();
    }
    if (j == 0) out[gi] = s_red[0] + bo[0];
}

// ---------------- launch ----------------------------------------------------
extern "C" void kernel_launch(void* const* d_in, const int* in_sizes, int n_in,
                              void* d_out, int out_size) {
    const float* x    = (const float*)d_in[0];
    const int*   esrc = (const int*)  d_in[1];
    const int*   edst = (const int*)  d_in[2];
    const float* ew   = (const float*)d_in[3];
    const int*   seg  = (const int*)  d_in[4];
    const float* W1   = (const float*)d_in[5];
    const float* b1   = (const float*)d_in[6];
    const float* W2   = (const float*)d_in[7];
    const float* b2   = (const float*)d_in[8];
    const float* Wd   = (const float*)d_in[9];
    const float* bd   = (const float*)d_in[10];
    const float* Wo   = (const float*)d_in[11];
    const float* bo   = (const float*)d_in[12];
    float* out = (float*)d_out;

    float* bufA; cudaGetSymbolAddress((void**)&bufA, g_bufA);
    float* bufB; cudaGetSymbolAddress((void**)&bufB, g_bufB);
    float* Wt1;  cudaGetSymbolAddress((void**)&Wt1,  g_Wt1);
    float* Wt2;  cudaGetSymbolAddress((void**)&Wt2,  g_Wt2);

    const size_t smem_bytes = (size_t)2 * 6144 * sizeof(uint32_t);   // 48KB

    // --- weight transposes (tiny) ---
    {
        dim3 blk(32, 8);
        dim3 g1(HIDDEN / 32, F_IN / 32);
        transpose_kernel<<<g1, blk>>>(W1, Wt1, F_IN, HIDDEN);
        dim3 g2(HIDDEN / 32, HIDDEN / 32);
        transpose_kernel<<<g2, blk>>>(W2, Wt2, HIDDEN, HIDDEN);
    }

    // --- CSR build (by destination) ---
    zero_rowptr_kernel<<<(N_NODES + 256) / 256, 256>>>();
    count_kernel<<<(N_EDGES + 255) / 256, 256>>>(edst);
    scan_kernel<<<1, 1024>>>();   // also initializes g_fill
    scatter_kernel<<<(N_EDGES + 255) / 256, 256>>>(esrc, edst, ew);

    const int n_mtiles = (N_NODES + 127) / 128;

    // --- layer 1: s0 = spmm(x) [N,128]; h1 = relu(s0 @ W1 + b1) ---
    spmm_kernel<F_IN><<<(N_NODES + 7) / 8, 256>>>(x, bufA);
    mma_gemm_kernel<F_IN, true><<<dim3(4, n_mtiles), 256, smem_bytes>>>(
        bufA, Wt1, b1, bufB, N_NODES);

    // --- layer 2: s1 = spmm(h1) [N,256]; h2 = relu(s1 @ W2 + b2) ---
    spmm_kernel<HIDDEN><<<(N_NODES + 7) / 8, 256>>>(bufB, bufA);
    mma_gemm_kernel<HIDDEN, true><<<dim3(4, n_mtiles), 256, smem_bytes>>>(
        bufA, Wt2, b2, bufB, N_NODES);

    // --- pool + head ---
    pool_kernel<<<N_GRAPHS, HIDDEN>>>(bufB, seg);
    head_kernel<<<N_GRAPHS, HIDDEN>>>(Wd, bd, Wo, bo, out);
}